// round 8
// baseline (speedup 1.0000x reference)
#include <cuda_runtime.h>
#include <cuda_fp16.h>
#include <cstdint>

// ClusteredLinear via cluster-paired fp16-split mma.sync GEMM.
// out[b,c,p] = sum_s x[b,c,s]*W[cl[c],p,s] + bias[cl[c],p]
// R7: KC=64 (12 chunks, half the barriers of R6), 3-stage cp.async pipeline,
// ROWB=144 (conflict-free ldmatrix). 2-pass fp16 split (x = xh + xl exactly,
// W ~= wh; dropped term ~2^-11 relative).
// 512 threads / 16 warps (8M x 2N, warp tile m16n56).

#define B_DIM 64
#define C_DIM 862
#define S_DIM 720
#define P_DIM 336
#define NCLUST 8

#define TILE_N 112
#define KC 64
#define NCHUNKS 12          // 11 full + 16-elem zero-padded tail
#define NSTAGES 3
#define NTILES 435
#define NPAD 880

#define ROWB 144                      // padded smem row stride (bytes), 128B data
#define OFF_AH 0
#define OFF_AL (128*ROWB)             // 18432
#define OFF_BH (OFF_AL + 128*ROWB)    // 36864
#define STAGE_B (OFF_BH + TILE_N*ROWB)   // 52992
#define SMEM_TOTAL (NSTAGES*STAGE_B)     // 158976

// ---- scratch ----
__device__ __half g_xh[(size_t)B_DIM*C_DIM*S_DIM];
__device__ __half g_xl[(size_t)B_DIM*C_DIM*S_DIM];
__device__ __half g_wh[(size_t)NCLUST*P_DIM*S_DIM];
__device__ int g_order[NPAD];

// ---- PTX helpers (family-portable) ----
__device__ __forceinline__ uint32_t smem_u32(const void* p) {
    uint32_t a;
    asm("{ .reg .u64 t; cvta.to.shared.u64 t, %1; cvt.u32.u64 %0, t; }" : "=r"(a) : "l"(p));
    return a;
}
#define CP16(dst,src) asm volatile("cp.async.cg.shared.global [%0], [%1], 16;" :: "r"(dst), "l"(src) : "memory")
#define CP_COMMIT()   asm volatile("cp.async.commit_group;" ::: "memory")
#define CP_WAIT(n)    asm volatile("cp.async.wait_group %0;" :: "n"(n) : "memory")
#define ZERO16(a)     asm volatile("st.shared.v4.b32 [%0], {%1,%1,%1,%1};" :: "r"(a), "r"(0) : "memory")

#define LDSM4(r, a) asm volatile("ldmatrix.sync.aligned.m8n8.x4.shared.b16 {%0,%1,%2,%3}, [%4];" \
    : "=r"((r)[0]),"=r"((r)[1]),"=r"((r)[2]),"=r"((r)[3]) : "r"(a))
#define LDSM2(r, a) asm volatile("ldmatrix.sync.aligned.m8n8.x2.shared.b16 {%0,%1}, [%2];" \
    : "=r"((r)[0]),"=r"((r)[1]) : "r"(a))
#define MMA(c, a, b) asm volatile( \
    "mma.sync.aligned.m16n8k16.row.col.f32.f16.f16.f32 " \
    "{%0,%1,%2,%3},{%4,%5,%6,%7},{%8,%9},{%0,%1,%2,%3};" \
    : "+f"((c)[0]),"+f"((c)[1]),"+f"((c)[2]),"+f"((c)[3]) \
    : "r"((a)[0]),"r"((a)[1]),"r"((a)[2]),"r"((a)[3]),"r"((b)[0]),"r"((b)[1]))

// ---- prep kernels ----
__global__ void convert_x(const float* __restrict__ src) {
    size_t i = (size_t)blockIdx.x * blockDim.x + threadIdx.x;
    const size_t n4 = (size_t)B_DIM * C_DIM * S_DIM / 4;
    if (i >= n4) return;
    float4 v = ((const float4*)src)[i];
    float vv[4] = {v.x, v.y, v.z, v.w};
    __half h[4], l[4];
    #pragma unroll
    for (int j = 0; j < 4; ++j) {
        h[j] = __float2half_rn(vv[j]);
        l[j] = __float2half_rn(vv[j] - __half2float(h[j]));
    }
    ((uint2*)g_xh)[i] = *(uint2*)h;
    ((uint2*)g_xl)[i] = *(uint2*)l;
}
__global__ void convert_w(const float* __restrict__ src) {
    size_t i = (size_t)blockIdx.x * blockDim.x + threadIdx.x;
    const size_t n4 = (size_t)NCLUST * P_DIM * S_DIM / 4;
    if (i >= n4) return;
    float4 v = ((const float4*)src)[i];
    float vv[4] = {v.x, v.y, v.z, v.w};
    __half h[4];
    #pragma unroll
    for (int j = 0; j < 4; ++j) h[j] = __float2half_rn(vv[j]);
    ((uint2*)g_wh)[i] = *(uint2*)h;
}

__global__ void build_order(const int* __restrict__ clusters) {
    __shared__ int cl[C_DIM];
    __shared__ int cnt[NCLUST];
    int t = threadIdx.x;
    for (int i = t; i < C_DIM; i += blockDim.x) {
        int k = clusters[i];
        cl[i] = min(max(k, 0), NCLUST - 1);
    }
    for (int i = t; i < NPAD; i += blockDim.x) g_order[i] = -1;
    __syncthreads();
    if (t < NCLUST) {
        int c = 0;
        for (int i = 0; i < C_DIM; ++i) c += (cl[i] == t);
        cnt[t] = c;
    }
    __syncthreads();
    if (t < C_DIM) {
        int k = cl[t];
        int off = 0;
        for (int j = 0; j < NCLUST; ++j) if (j < k) off += (cnt[j] + 1) & ~1;
        int rank = 0;
        for (int i = 0; i < t; ++i) rank += (cl[i] == k);
        g_order[off + rank] = t;
    }
}

// ---- GEMM ----
__device__ __forceinline__ void load_stage(uint32_t st, int k0, bool tail,
                                           int ch0, int ch1, int kcl,
                                           int n_base, int tid) {
    // A: 128 rows x 128B of K, hi+lo. 1024 vec-slots over 512 threads.
    #pragma unroll
    for (int v = tid; v < 1024; v += 512) {
        int r = v >> 3, q = v & 7;
        int b = r & 63;
        int c = (r >> 6) ? ch1 : ch0;
        size_t so = ((size_t)b * C_DIM + c) * S_DIM + k0 + q * 8;
        uint32_t d = st + OFF_AH + r * ROWB + q * 16;
        if (!tail || q < 2) {
            CP16(d, g_xh + so);
            CP16(d + (OFF_AL - OFF_AH), g_xl + so);
        } else {
            ZERO16(d);
            ZERO16(d + (OFF_AL - OFF_AH));
        }
    }
    // B: 112 rows x 128B of K, hi only. 896 vec-slots.
    #pragma unroll
    for (int v = tid; v < 896; v += 512) {
        int r = v >> 3, q = v & 7;
        size_t so = ((size_t)kcl * P_DIM + n_base + r) * S_DIM + k0 + q * 8;
        uint32_t d = st + OFF_BH + r * ROWB + q * 16;
        if (!tail || q < 2) {
            CP16(d, g_wh + so);
        } else {
            ZERO16(d);
        }
    }
}

__global__ __launch_bounds__(512, 1)
void gemm_kernel(const int* __restrict__ clusters,
                 const float* __restrict__ bias,
                 float* __restrict__ out) {
    extern __shared__ char smem[];
    const uint32_t sbase = smem_u32(smem);
    const int tid  = threadIdx.x;
    const int lane = tid & 31;
    const int wid  = tid >> 5;
    const int warpM = wid & 7;      // 8 M-warps (m16 each)
    const int warpN = wid >> 3;     // 2 N-warps (n56 each)
    const int mrow0 = warpM * 16;
    const int nrow0 = warpN * 56;

    const int tile   = blockIdx.y;
    const int n_base = blockIdx.x * TILE_N;

    int ch0 = g_order[2 * tile];
    int ch1 = g_order[2 * tile + 1];
    if (ch0 < 0) return;
    const bool valid1 = (ch1 >= 0);
    if (!valid1) ch1 = ch0;
    int kcl = clusters[ch0];
    kcl = min(max(kcl, 0), NCLUST - 1);

    float acc[7][4] = {};

    // ldmatrix base addresses (stage 0; add stage offset + k-offset per use).
    const uint32_t a_addr0 = sbase + OFF_AH +
        (uint32_t)(mrow0 + (lane & 15)) * ROWB + ((lane >> 4) << 4);
    const uint32_t b_addr_pair0 = sbase + OFF_BH +
        (uint32_t)(nrow0 + ((lane >> 4) << 3) + (lane & 7)) * ROWB +
        (((lane >> 3) & 1) << 4);
    const uint32_t b_addr_last0 = sbase + OFF_BH +
        (uint32_t)(nrow0 + 48 + (lane & 7)) * ROWB + (((lane >> 3) & 1) << 4);

    // prologue: stages 0..NSTAGES-2
    #pragma unroll
    for (int s = 0; s < NSTAGES - 1; ++s) {
        load_stage(sbase + s * STAGE_B, s * KC, false, ch0, ch1, kcl, n_base, tid);
        CP_COMMIT();
    }

    int stage = 0;
    for (int chunk = 0; chunk < NCHUNKS; ++chunk) {
        CP_WAIT(NSTAGES - 2);
        __syncthreads();

        const int nx = chunk + NSTAGES - 1;
        if (nx < NCHUNKS) {
            int nstage = stage + NSTAGES - 1;
            if (nstage >= NSTAGES) nstage -= NSTAGES;
            load_stage(sbase + nstage * STAGE_B, nx * KC,
                       nx == NCHUNKS - 1, ch0, ch1, kcl, n_base, tid);
        }
        CP_COMMIT();

        const uint32_t so = (uint32_t)stage * STAGE_B;
        #pragma unroll
        for (int ks = 0; ks < 4; ++ks) {
            const int kb = ks * 32;
            uint32_t ah[4], al[4];
            LDSM4(ah, a_addr0 + so + kb);
            LDSM4(al, a_addr0 + so + kb + (OFF_AL - OFF_AH));

            uint32_t bh[7][2];
            #pragma unroll
            for (int p = 0; p < 3; ++p) {
                uint32_t a = b_addr_pair0 + so + kb + (uint32_t)p * 16 * ROWB;
                uint32_t r4[4];
                LDSM4(r4, a);
                bh[2*p][0] = r4[0]; bh[2*p][1] = r4[1];
                bh[2*p+1][0] = r4[2]; bh[2*p+1][1] = r4[3];
            }
            LDSM2(bh[6], b_addr_last0 + so + kb);

            #pragma unroll
            for (int nf = 0; nf < 7; ++nf) {
                MMA(acc[nf], ah, bh[nf]);
                MMA(acc[nf], al, bh[nf]);
            }
        }
        if (++stage == NSTAGES) stage = 0;
    }

    // epilogue: bias + store
    const float* biasrow = bias + (size_t)kcl * P_DIM + n_base + nrow0;
    const int m0 = mrow0 + (lane >> 2);
    const bool hi_half = (m0 >= 64);
    if (!hi_half || valid1) {
        const int b0 = hi_half ? m0 - 64 : m0;
        const int cc = hi_half ? ch1 : ch0;
        float* o0 = out + ((size_t)b0 * C_DIM + cc) * P_DIM + n_base + nrow0;
        float* o1 = o0 + (size_t)8 * C_DIM * P_DIM;
        #pragma unroll
        for (int nf = 0; nf < 7; ++nf) {
            const int col = nf * 8 + (lane & 3) * 2;
            float2 bb = *(const float2*)(biasrow + col);
            float2 v0, v1;
            v0.x = acc[nf][0] + bb.x;
            v0.y = acc[nf][1] + bb.y;
            v1.x = acc[nf][2] + bb.x;
            v1.y = acc[nf][3] + bb.y;
            *(float2*)(o0 + col) = v0;
            *(float2*)(o1 + col) = v1;
        }
    }
}

extern "C" void kernel_launch(void* const* d_in, const int* in_sizes, int n_in,
                              void* d_out, int out_size) {
    const float* x        = (const float*)d_in[0];
    const int*   clusters = (const int*)d_in[1];
    const float* W        = (const float*)d_in[2];
    const float* bias     = (const float*)d_in[3];
    float*       out      = (float*)d_out;

    cudaFuncSetAttribute(gemm_kernel, cudaFuncAttributeMaxDynamicSharedMemorySize, SMEM_TOTAL);

    convert_x<<<(int)(((size_t)B_DIM*C_DIM*S_DIM/4 + 255)/256), 256>>>(x);
    convert_w<<<(int)(((size_t)NCLUST*P_DIM*S_DIM/4 + 255)/256), 256>>>(W);
    build_order<<<1, 896>>>(clusters);
    gemm_kernel<<<dim3(3, NTILES), 512, SMEM_TOTAL>>>(clusters, bias, out);
}

// round 9
// speedup vs baseline: 1.9039x; 1.9039x over previous
#include <cuda_runtime.h>
#include <cuda_fp16.h>
#include <cstdint>

// ClusteredLinear via cluster-paired fp16 mma.sync GEMM.
// out[b,c,p] = sum_s x[b,c,s]*W[cl[c],p,s] + bias[cl[c],p]
// R8: revert to R6 pipeline shape (KC=32, 4 stages — R7's KC=64/3-stage
// regressed), and drop to single-pass pure fp16 (both x and W rounded to
// fp16, fp32 accumulate). Independent rounding errors: measured 2.17e-4
// (w-only) -> predicted ~3.1e-4 combined, under the 1e-3 gate.
// 512 threads / 16 warps (8M x 2N, warp tile m16n56), single-barrier
// 4-stage cp.async pipeline, LDSM x4-paired B fragment loads.

#define B_DIM 64
#define C_DIM 862
#define S_DIM 720
#define P_DIM 336
#define NCLUST 8

#define TILE_N 112
#define KC 32
#define NCHUNKS 23          // 22 full + 16-elem zero-padded tail
#define NSTAGES 4
#define NTILES 435
#define NPAD 880

#define ROWB 80                       // padded smem row stride (bytes)
#define OFF_A 0
#define OFF_B (128*ROWB)              // 10240
#define STAGE_B (OFF_B + TILE_N*ROWB)    // 19200
#define SMEM_TOTAL (NSTAGES*STAGE_B)     // 76800

// ---- scratch ----
__device__ __half g_xh[(size_t)B_DIM*C_DIM*S_DIM];
__device__ __half g_wh[(size_t)NCLUST*P_DIM*S_DIM];
__device__ int g_order[NPAD];

// ---- PTX helpers (family-portable) ----
__device__ __forceinline__ uint32_t smem_u32(const void* p) {
    uint32_t a;
    asm("{ .reg .u64 t; cvta.to.shared.u64 t, %1; cvt.u32.u64 %0, t; }" : "=r"(a) : "l"(p));
    return a;
}
#define CP16(dst,src) asm volatile("cp.async.cg.shared.global [%0], [%1], 16;" :: "r"(dst), "l"(src) : "memory")
#define CP_COMMIT()   asm volatile("cp.async.commit_group;" ::: "memory")
#define CP_WAIT(n)    asm volatile("cp.async.wait_group %0;" :: "n"(n) : "memory")
#define ZERO16(a)     asm volatile("st.shared.v4.b32 [%0], {%1,%1,%1,%1};" :: "r"(a), "r"(0) : "memory")

#define LDSM4(r, a) asm volatile("ldmatrix.sync.aligned.m8n8.x4.shared.b16 {%0,%1,%2,%3}, [%4];" \
    : "=r"((r)[0]),"=r"((r)[1]),"=r"((r)[2]),"=r"((r)[3]) : "r"(a))
#define LDSM2(r, a) asm volatile("ldmatrix.sync.aligned.m8n8.x2.shared.b16 {%0,%1}, [%2];" \
    : "=r"((r)[0]),"=r"((r)[1]) : "r"(a))
#define MMA(c, a, b) asm volatile( \
    "mma.sync.aligned.m16n8k16.row.col.f32.f16.f16.f32 " \
    "{%0,%1,%2,%3},{%4,%5,%6,%7},{%8,%9},{%0,%1,%2,%3};" \
    : "+f"((c)[0]),"+f"((c)[1]),"+f"((c)[2]),"+f"((c)[3]) \
    : "r"((a)[0]),"r"((a)[1]),"r"((a)[2]),"r"((a)[3]),"r"((b)[0]),"r"((b)[1]))

// ---- prep kernels ----
__global__ void convert_x(const float* __restrict__ src) {
    size_t i = (size_t)blockIdx.x * blockDim.x + threadIdx.x;
    const size_t n4 = (size_t)B_DIM * C_DIM * S_DIM / 4;
    if (i >= n4) return;
    float4 v = ((const float4*)src)[i];
    float vv[4] = {v.x, v.y, v.z, v.w};
    __half h[4];
    #pragma unroll
    for (int j = 0; j < 4; ++j) h[j] = __float2half_rn(vv[j]);
    ((uint2*)g_xh)[i] = *(uint2*)h;
}
__global__ void convert_w(const float* __restrict__ src) {
    size_t i = (size_t)blockIdx.x * blockDim.x + threadIdx.x;
    const size_t n4 = (size_t)NCLUST * P_DIM * S_DIM / 4;
    if (i >= n4) return;
    float4 v = ((const float4*)src)[i];
    float vv[4] = {v.x, v.y, v.z, v.w};
    __half h[4];
    #pragma unroll
    for (int j = 0; j < 4; ++j) h[j] = __float2half_rn(vv[j]);
    ((uint2*)g_wh)[i] = *(uint2*)h;
}

__global__ void build_order(const int* __restrict__ clusters) {
    __shared__ int cl[C_DIM];
    __shared__ int cnt[NCLUST];
    int t = threadIdx.x;
    for (int i = t; i < C_DIM; i += blockDim.x) {
        int k = clusters[i];
        cl[i] = min(max(k, 0), NCLUST - 1);
    }
    for (int i = t; i < NPAD; i += blockDim.x) g_order[i] = -1;
    __syncthreads();
    if (t < NCLUST) {
        int c = 0;
        for (int i = 0; i < C_DIM; ++i) c += (cl[i] == t);
        cnt[t] = c;
    }
    __syncthreads();
    if (t < C_DIM) {
        int k = cl[t];
        int off = 0;
        for (int j = 0; j < NCLUST; ++j) if (j < k) off += (cnt[j] + 1) & ~1;
        int rank = 0;
        for (int i = 0; i < t; ++i) rank += (cl[i] == k);
        g_order[off + rank] = t;
    }
}

// ---- GEMM ----
__device__ __forceinline__ void load_stage(uint32_t st, int k0, bool tail,
                                           int ch0, int ch1, int kcl,
                                           int n_base, int tid) {
    // A: 128 rows x 64B of K. 512 threads -> one 16B vec each.
    {
        int r = tid >> 2, q = tid & 3;
        int b = r & 63;
        int c = (r >> 6) ? ch1 : ch0;
        size_t so = ((size_t)b * C_DIM + c) * S_DIM + k0 + q * 8;
        uint32_t d = st + OFF_A + r * ROWB + q * 16;
        if (!tail || q < 2) CP16(d, g_xh + so);
        else                ZERO16(d);
    }
    // B: 112 rows x 64B of K. threads 0..447.
    if (tid < 448) {
        int r = tid >> 2, q = tid & 3;
        size_t so = ((size_t)kcl * P_DIM + n_base + r) * S_DIM + k0 + q * 8;
        uint32_t d = st + OFF_B + r * ROWB + q * 16;
        if (!tail || q < 2) CP16(d, g_wh + so);
        else                ZERO16(d);
    }
}

__global__ __launch_bounds__(512, 1)
void gemm_kernel(const int* __restrict__ clusters,
                 const float* __restrict__ bias,
                 float* __restrict__ out) {
    extern __shared__ char smem[];
    const uint32_t sbase = smem_u32(smem);
    const int tid  = threadIdx.x;
    const int lane = tid & 31;
    const int wid  = tid >> 5;
    const int warpM = wid & 7;      // 8 M-warps (m16 each)
    const int warpN = wid >> 3;     // 2 N-warps (n56 each)
    const int mrow0 = warpM * 16;
    const int nrow0 = warpN * 56;

    const int tile   = blockIdx.y;
    const int n_base = blockIdx.x * TILE_N;

    int ch0 = g_order[2 * tile];
    int ch1 = g_order[2 * tile + 1];
    if (ch0 < 0) return;
    const bool valid1 = (ch1 >= 0);
    if (!valid1) ch1 = ch0;
    int kcl = clusters[ch0];
    kcl = min(max(kcl, 0), NCLUST - 1);

    float acc[7][4] = {};

    // ldmatrix base addresses (stage 0; add stage offset per chunk).
    const uint32_t a_addr0 = sbase + OFF_A +
        (uint32_t)(mrow0 + (lane & 15)) * ROWB + ((lane >> 4) << 4);
    const uint32_t b_addr_pair0 = sbase + OFF_B +
        (uint32_t)(nrow0 + ((lane >> 4) << 3) + (lane & 7)) * ROWB +
        (((lane >> 3) & 1) << 4);
    const uint32_t b_addr_last0 = sbase + OFF_B +
        (uint32_t)(nrow0 + 48 + (lane & 7)) * ROWB + (((lane >> 3) & 1) << 4);

    // prologue: stages 0..NSTAGES-2
    #pragma unroll
    for (int s = 0; s < NSTAGES - 1; ++s) {
        load_stage(sbase + s * STAGE_B, s * KC, false, ch0, ch1, kcl, n_base, tid);
        CP_COMMIT();
    }

    for (int chunk = 0; chunk < NCHUNKS; ++chunk) {
        CP_WAIT(NSTAGES - 2);
        __syncthreads();

        const int nx = chunk + NSTAGES - 1;
        if (nx < NCHUNKS)
            load_stage(sbase + (nx & (NSTAGES - 1)) * STAGE_B, nx * KC,
                       nx == NCHUNKS - 1, ch0, ch1, kcl, n_base, tid);
        CP_COMMIT();

        const uint32_t so = (uint32_t)(chunk & (NSTAGES - 1)) * STAGE_B;
        #pragma unroll
        for (int ks = 0; ks < 2; ++ks) {
            const int kb = ks * 32;
            uint32_t ah[4];
            LDSM4(ah, a_addr0 + so + kb);

            uint32_t bh[7][2];
            #pragma unroll
            for (int p = 0; p < 3; ++p) {
                uint32_t a = b_addr_pair0 + so + kb + (uint32_t)p * 16 * ROWB;
                uint32_t r4[4];
                LDSM4(r4, a);
                bh[2*p][0] = r4[0]; bh[2*p][1] = r4[1];
                bh[2*p+1][0] = r4[2]; bh[2*p+1][1] = r4[3];
            }
            LDSM2(bh[6], b_addr_last0 + so + kb);

            #pragma unroll
            for (int nf = 0; nf < 7; ++nf)
                MMA(acc[nf], ah, bh[nf]);
        }
    }

    // epilogue: bias + store
    const float* biasrow = bias + (size_t)kcl * P_DIM + n_base + nrow0;
    const int m0 = mrow0 + (lane >> 2);
    const bool hi_half = (m0 >= 64);
    if (!hi_half || valid1) {
        const int b0 = hi_half ? m0 - 64 : m0;
        const int cc = hi_half ? ch1 : ch0;
        float* o0 = out + ((size_t)b0 * C_DIM + cc) * P_DIM + n_base + nrow0;
        float* o1 = o0 + (size_t)8 * C_DIM * P_DIM;
        #pragma unroll
        for (int nf = 0; nf < 7; ++nf) {
            const int col = nf * 8 + (lane & 3) * 2;
            float2 bb = *(const float2*)(biasrow + col);
            float2 v0, v1;
            v0.x = acc[nf][0] + bb.x;
            v0.y = acc[nf][1] + bb.y;
            v1.x = acc[nf][2] + bb.x;
            v1.y = acc[nf][3] + bb.y;
            *(float2*)(o0 + col) = v0;
            *(float2*)(o1 + col) = v1;
        }
    }
}

extern "C" void kernel_launch(void* const* d_in, const int* in_sizes, int n_in,
                              void* d_out, int out_size) {
    const float* x        = (const float*)d_in[0];
    const int*   clusters = (const int*)d_in[1];
    const float* W        = (const float*)d_in[2];
    const float* bias     = (const float*)d_in[3];
    float*       out      = (float*)d_out;

    cudaFuncSetAttribute(gemm_kernel, cudaFuncAttributeMaxDynamicSharedMemorySize, SMEM_TOTAL);

    convert_x<<<(int)(((size_t)B_DIM*C_DIM*S_DIM/4 + 255)/256), 256>>>(x);
    convert_w<<<(int)(((size_t)NCLUST*P_DIM*S_DIM/4 + 255)/256), 256>>>(W);
    build_order<<<1, 896>>>(clusters);
    gemm_kernel<<<dim3(3, NTILES), 512, SMEM_TOTAL>>>(clusters, bias, out);
}

// round 10
// speedup vs baseline: 2.1484x; 1.1284x over previous
#include <cuda_runtime.h>
#include <cuda_fp16.h>
#include <cstdint>

// ClusteredLinear via fp16 mma.sync GEMM, one channel per CTA.
// out[b,c,p] = sum_s x[b,c,s]*W[cl[c],p,s] + bias[cl[c],p]
// R9: tile M=64 (one channel x 64 batch) x N=112, 256 threads / 8 warps
// (4M x 2N, warp tile m16n56), 4-stage KC=32 cp.async pipeline.
// Stage 14.1KB -> 56.3KB total smem, ~100 regs -> 2 CTAs/SM: two
// independent pipelines per SM hide the sync/latency bubbles that bound R8.
// Single-pass fp16 (x,W rounded, fp32 accum): rel_err ~3.0e-4 (measured).

#define B_DIM 64
#define C_DIM 862
#define S_DIM 720
#define P_DIM 336
#define NCLUST 8

#define TILE_N 112
#define KC 32
#define NCHUNKS 23          // 22 full + 16-elem zero-padded tail
#define NSTAGES 4

#define ROWB 80                       // padded smem row stride (bytes)
#define OFF_A 0
#define OFF_B (64*ROWB)               // 5120
#define STAGE_B (OFF_B + TILE_N*ROWB)    // 14080
#define SMEM_TOTAL (NSTAGES*STAGE_B)     // 56320

// ---- scratch ----
__device__ __half g_xh[(size_t)B_DIM*C_DIM*S_DIM];
__device__ __half g_wh[(size_t)NCLUST*P_DIM*S_DIM];

// ---- PTX helpers (family-portable) ----
__device__ __forceinline__ uint32_t smem_u32(const void* p) {
    uint32_t a;
    asm("{ .reg .u64 t; cvta.to.shared.u64 t, %1; cvt.u32.u64 %0, t; }" : "=r"(a) : "l"(p));
    return a;
}
#define CP16(dst,src) asm volatile("cp.async.cg.shared.global [%0], [%1], 16;" :: "r"(dst), "l"(src) : "memory")
#define CP_COMMIT()   asm volatile("cp.async.commit_group;" ::: "memory")
#define CP_WAIT(n)    asm volatile("cp.async.wait_group %0;" :: "n"(n) : "memory")
#define ZERO16(a)     asm volatile("st.shared.v4.b32 [%0], {%1,%1,%1,%1};" :: "r"(a), "r"(0) : "memory")

#define LDSM4(r, a) asm volatile("ldmatrix.sync.aligned.m8n8.x4.shared.b16 {%0,%1,%2,%3}, [%4];" \
    : "=r"((r)[0]),"=r"((r)[1]),"=r"((r)[2]),"=r"((r)[3]) : "r"(a))
#define LDSM2(r, a) asm volatile("ldmatrix.sync.aligned.m8n8.x2.shared.b16 {%0,%1}, [%2];" \
    : "=r"((r)[0]),"=r"((r)[1]) : "r"(a))
#define MMA(c, a, b) asm volatile( \
    "mma.sync.aligned.m16n8k16.row.col.f32.f16.f16.f32 " \
    "{%0,%1,%2,%3},{%4,%5,%6,%7},{%8,%9},{%0,%1,%2,%3};" \
    : "+f"((c)[0]),"+f"((c)[1]),"+f"((c)[2]),"+f"((c)[3]) \
    : "r"((a)[0]),"r"((a)[1]),"r"((a)[2]),"r"((a)[3]),"r"((b)[0]),"r"((b)[1]))

// ---- prep kernels ----
__global__ void convert_x(const float* __restrict__ src) {
    size_t i = (size_t)blockIdx.x * blockDim.x + threadIdx.x;
    const size_t n4 = (size_t)B_DIM * C_DIM * S_DIM / 4;
    if (i >= n4) return;
    float4 v = ((const float4*)src)[i];
    float vv[4] = {v.x, v.y, v.z, v.w};
    __half h[4];
    #pragma unroll
    for (int j = 0; j < 4; ++j) h[j] = __float2half_rn(vv[j]);
    ((uint2*)g_xh)[i] = *(uint2*)h;
}
__global__ void convert_w(const float* __restrict__ src) {
    size_t i = (size_t)blockIdx.x * blockDim.x + threadIdx.x;
    const size_t n4 = (size_t)NCLUST * P_DIM * S_DIM / 4;
    if (i >= n4) return;
    float4 v = ((const float4*)src)[i];
    float vv[4] = {v.x, v.y, v.z, v.w};
    __half h[4];
    #pragma unroll
    for (int j = 0; j < 4; ++j) h[j] = __float2half_rn(vv[j]);
    ((uint2*)g_wh)[i] = *(uint2*)h;
}

// ---- GEMM ----
__device__ __forceinline__ void load_stage(uint32_t st, int k0, bool tail,
                                           int ch, int kcl,
                                           int n_base, int tid) {
    // A: 64 rows x 64B of K. 256 slots -> exactly one per thread.
    {
        int r = tid >> 2, q = tid & 3;
        size_t so = ((size_t)r * C_DIM + ch) * S_DIM + k0 + q * 8;
        uint32_t d = st + OFF_A + r * ROWB + q * 16;
        if (!tail || q < 2) CP16(d, g_xh + so);
        else                ZERO16(d);
    }
    // B: 112 rows x 64B of K. 448 slots over 256 threads.
    #pragma unroll
    for (int v = tid; v < 448; v += 256) {
        int r = v >> 2, q = v & 3;
        size_t so = ((size_t)kcl * P_DIM + n_base + r) * S_DIM + k0 + q * 8;
        uint32_t d = st + OFF_B + r * ROWB + q * 16;
        if (!tail || q < 2) CP16(d, g_wh + so);
        else                ZERO16(d);
    }
}

__global__ __launch_bounds__(256, 2)
void gemm_kernel(const int* __restrict__ clusters,
                 const float* __restrict__ bias,
                 float* __restrict__ out) {
    extern __shared__ char smem[];
    const uint32_t sbase = smem_u32(smem);
    const int tid  = threadIdx.x;
    const int lane = tid & 31;
    const int wid  = tid >> 5;
    const int warpM = wid & 3;      // 4 M-warps (m16 each)
    const int warpN = wid >> 2;     // 2 N-warps (n56 each)
    const int mrow0 = warpM * 16;
    const int nrow0 = warpN * 56;

    const int ch     = blockIdx.y;           // channel
    const int n_base = blockIdx.x * TILE_N;

    int kcl = clusters[ch];
    kcl = min(max(kcl, 0), NCLUST - 1);

    float acc[7][4] = {};

    // ldmatrix base addresses (stage 0; add stage offset per chunk).
    const uint32_t a_addr0 = sbase + OFF_A +
        (uint32_t)(mrow0 + (lane & 15)) * ROWB + ((lane >> 4) << 4);
    const uint32_t b_addr_pair0 = sbase + OFF_B +
        (uint32_t)(nrow0 + ((lane >> 4) << 3) + (lane & 7)) * ROWB +
        (((lane >> 3) & 1) << 4);
    const uint32_t b_addr_last0 = sbase + OFF_B +
        (uint32_t)(nrow0 + 48 + (lane & 7)) * ROWB + (((lane >> 3) & 1) << 4);

    // prologue: stages 0..NSTAGES-2
    #pragma unroll
    for (int s = 0; s < NSTAGES - 1; ++s) {
        load_stage(sbase + s * STAGE_B, s * KC, false, ch, kcl, n_base, tid);
        CP_COMMIT();
    }

    for (int chunk = 0; chunk < NCHUNKS; ++chunk) {
        CP_WAIT(NSTAGES - 2);
        __syncthreads();

        const int nx = chunk + NSTAGES - 1;
        if (nx < NCHUNKS)
            load_stage(sbase + (nx & (NSTAGES - 1)) * STAGE_B, nx * KC,
                       nx == NCHUNKS - 1, ch, kcl, n_base, tid);
        CP_COMMIT();

        const uint32_t so = (uint32_t)(chunk & (NSTAGES - 1)) * STAGE_B;
        #pragma unroll
        for (int ks = 0; ks < 2; ++ks) {
            const int kb = ks * 32;
            uint32_t ah[4];
            LDSM4(ah, a_addr0 + so + kb);

            uint32_t bh[7][2];
            #pragma unroll
            for (int p = 0; p < 3; ++p) {
                uint32_t a = b_addr_pair0 + so + kb + (uint32_t)p * 16 * ROWB;
                uint32_t r4[4];
                LDSM4(r4, a);
                bh[2*p][0] = r4[0]; bh[2*p][1] = r4[1];
                bh[2*p+1][0] = r4[2]; bh[2*p+1][1] = r4[3];
            }
            LDSM2(bh[6], b_addr_last0 + so + kb);

            #pragma unroll
            for (int nf = 0; nf < 7; ++nf)
                MMA(acc[nf], ah, bh[nf]);
        }
    }

    // epilogue: bias + store
    const float* biasrow = bias + (size_t)kcl * P_DIM + n_base + nrow0;
    const int b0 = mrow0 + (lane >> 2);      // batch row (0..63)
    float* o0 = out + ((size_t)b0 * C_DIM + ch) * P_DIM + n_base + nrow0;
    float* o1 = o0 + (size_t)8 * C_DIM * P_DIM;
    #pragma unroll
    for (int nf = 0; nf < 7; ++nf) {
        const int col = nf * 8 + (lane & 3) * 2;
        float2 bb = *(const float2*)(biasrow + col);
        float2 v0, v1;
        v0.x = acc[nf][0] + bb.x;
        v0.y = acc[nf][1] + bb.y;
        v1.x = acc[nf][2] + bb.x;
        v1.y = acc[nf][3] + bb.y;
        *(float2*)(o0 + col) = v0;
        *(float2*)(o1 + col) = v1;
    }
}

extern "C" void kernel_launch(void* const* d_in, const int* in_sizes, int n_in,
                              void* d_out, int out_size) {
    const float* x        = (const float*)d_in[0];
    const int*   clusters = (const int*)d_in[1];
    const float* W        = (const float*)d_in[2];
    const float* bias     = (const float*)d_in[3];
    float*       out      = (float*)d_out;

    cudaFuncSetAttribute(gemm_kernel, cudaFuncAttributeMaxDynamicSharedMemorySize, SMEM_TOTAL);

    convert_x<<<(int)(((size_t)B_DIM*C_DIM*S_DIM/4 + 255)/256), 256>>>(x);
    convert_w<<<(int)(((size_t)NCLUST*P_DIM*S_DIM/4 + 255)/256), 256>>>(W);
    gemm_kernel<<<dim3(3, C_DIM), 256, SMEM_TOTAL>>>(clusters, bias, out);
}

// round 11
// speedup vs baseline: 2.4485x; 1.1397x over previous
#include <cuda_runtime.h>
#include <cuda_fp16.h>
#include <cstdint>

// ClusteredLinear via fp16 mma.sync GEMM, one channel per CTA.
// out[b,c,p] = sum_s x[b,c,s]*W[cl[c],p,s] + bias[cl[c],p]
// R10: 128 threads / 4 warps (2M x 2N), warp tile m32n56 -> B crossbar
// duplication x4 -> x2 (bytes/chunk 50.7KB -> 36.3KB), 4 CTAs/SM
// (56.3KB smem, <=128 regs). 4-stage KC=32 cp.async pipeline.
// Single-pass fp16 (x,W rounded, fp32 accum): rel_err ~3.0e-4 measured.

#define B_DIM 64
#define C_DIM 862
#define S_DIM 720
#define P_DIM 336
#define NCLUST 8

#define TILE_N 112
#define KC 32
#define NCHUNKS 23          // 22 full + 16-elem zero-padded tail
#define NSTAGES 4

#define ROWB 80                       // padded smem row stride (bytes)
#define OFF_A 0
#define OFF_B (64*ROWB)               // 5120
#define STAGE_B (OFF_B + TILE_N*ROWB)    // 14080
#define SMEM_TOTAL (NSTAGES*STAGE_B)     // 56320

// ---- scratch ----
__device__ __half g_xh[(size_t)B_DIM*C_DIM*S_DIM];
__device__ __half g_wh[(size_t)NCLUST*P_DIM*S_DIM];

// ---- PTX helpers (family-portable) ----
__device__ __forceinline__ uint32_t smem_u32(const void* p) {
    uint32_t a;
    asm("{ .reg .u64 t; cvta.to.shared.u64 t, %1; cvt.u32.u64 %0, t; }" : "=r"(a) : "l"(p));
    return a;
}
#define CP16(dst,src) asm volatile("cp.async.cg.shared.global [%0], [%1], 16;" :: "r"(dst), "l"(src) : "memory")
#define CP_COMMIT()   asm volatile("cp.async.commit_group;" ::: "memory")
#define CP_WAIT(n)    asm volatile("cp.async.wait_group %0;" :: "n"(n) : "memory")
#define ZERO16(a)     asm volatile("st.shared.v4.b32 [%0], {%1,%1,%1,%1};" :: "r"(a), "r"(0) : "memory")

#define LDSM4(r, a) asm volatile("ldmatrix.sync.aligned.m8n8.x4.shared.b16 {%0,%1,%2,%3}, [%4];" \
    : "=r"((r)[0]),"=r"((r)[1]),"=r"((r)[2]),"=r"((r)[3]) : "r"(a))
#define LDSM2(r, a) asm volatile("ldmatrix.sync.aligned.m8n8.x2.shared.b16 {%0,%1}, [%2];" \
    : "=r"((r)[0]),"=r"((r)[1]) : "r"(a))
#define MMA(c, a, b) asm volatile( \
    "mma.sync.aligned.m16n8k16.row.col.f32.f16.f16.f32 " \
    "{%0,%1,%2,%3},{%4,%5,%6,%7},{%8,%9},{%0,%1,%2,%3};" \
    : "+f"((c)[0]),"+f"((c)[1]),"+f"((c)[2]),"+f"((c)[3]) \
    : "r"((a)[0]),"r"((a)[1]),"r"((a)[2]),"r"((a)[3]),"r"((b)[0]),"r"((b)[1]))

// ---- prep kernels ----
__global__ void convert_x(const float* __restrict__ src) {
    size_t i = (size_t)blockIdx.x * blockDim.x + threadIdx.x;
    const size_t n4 = (size_t)B_DIM * C_DIM * S_DIM / 4;
    if (i >= n4) return;
    float4 v = ((const float4*)src)[i];
    float vv[4] = {v.x, v.y, v.z, v.w};
    __half h[4];
    #pragma unroll
    for (int j = 0; j < 4; ++j) h[j] = __float2half_rn(vv[j]);
    ((uint2*)g_xh)[i] = *(uint2*)h;
}
__global__ void convert_w(const float* __restrict__ src) {
    size_t i = (size_t)blockIdx.x * blockDim.x + threadIdx.x;
    const size_t n4 = (size_t)NCLUST * P_DIM * S_DIM / 4;
    if (i >= n4) return;
    float4 v = ((const float4*)src)[i];
    float vv[4] = {v.x, v.y, v.z, v.w};
    __half h[4];
    #pragma unroll
    for (int j = 0; j < 4; ++j) h[j] = __float2half_rn(vv[j]);
    ((uint2*)g_wh)[i] = *(uint2*)h;
}

// ---- GEMM ----
__device__ __forceinline__ void load_stage(uint32_t st, int k0, bool tail,
                                           int ch, int kcl,
                                           int n_base, int tid) {
    // A: 64 rows x 64B of K. 256 slots over 128 threads.
    #pragma unroll
    for (int v = tid; v < 256; v += 128) {
        int r = v >> 2, q = v & 3;
        size_t so = ((size_t)r * C_DIM + ch) * S_DIM + k0 + q * 8;
        uint32_t d = st + OFF_A + r * ROWB + q * 16;
        if (!tail || q < 2) CP16(d, g_xh + so);
        else                ZERO16(d);
    }
    // B: 112 rows x 64B of K. 448 slots over 128 threads.
    #pragma unroll
    for (int v = tid; v < 448; v += 128) {
        int r = v >> 2, q = v & 3;
        size_t so = ((size_t)kcl * P_DIM + n_base + r) * S_DIM + k0 + q * 8;
        uint32_t d = st + OFF_B + r * ROWB + q * 16;
        if (!tail || q < 2) CP16(d, g_wh + so);
        else                ZERO16(d);
    }
}

__global__ __launch_bounds__(128, 4)
void gemm_kernel(const int* __restrict__ clusters,
                 const float* __restrict__ bias,
                 float* __restrict__ out) {
    extern __shared__ char smem[];
    const uint32_t sbase = smem_u32(smem);
    const int tid  = threadIdx.x;
    const int lane = tid & 31;
    const int wid  = tid >> 5;
    const int warpM = wid & 1;      // 2 M-warps (m32 each)
    const int warpN = wid >> 1;     // 2 N-warps (n56 each)
    const int mrow0 = warpM * 32;
    const int nrow0 = warpN * 56;

    const int ch     = blockIdx.y;           // channel
    const int n_base = blockIdx.x * TILE_N;

    int kcl = clusters[ch];
    kcl = min(max(kcl, 0), NCLUST - 1);

    float acc[2][7][4] = {};

    // ldmatrix base addresses (stage 0; add stage offset per chunk).
    const uint32_t a_addr0 = sbase + OFF_A +
        (uint32_t)(mrow0 + (lane & 15)) * ROWB + ((lane >> 4) << 4);
    const uint32_t b_addr_pair0 = sbase + OFF_B +
        (uint32_t)(nrow0 + ((lane >> 4) << 3) + (lane & 7)) * ROWB +
        (((lane >> 3) & 1) << 4);
    const uint32_t b_addr_last0 = sbase + OFF_B +
        (uint32_t)(nrow0 + 48 + (lane & 7)) * ROWB + (((lane >> 3) & 1) << 4);

    // prologue: stages 0..NSTAGES-2
    #pragma unroll
    for (int s = 0; s < NSTAGES - 1; ++s) {
        load_stage(sbase + s * STAGE_B, s * KC, false, ch, kcl, n_base, tid);
        CP_COMMIT();
    }

    for (int chunk = 0; chunk < NCHUNKS; ++chunk) {
        CP_WAIT(NSTAGES - 2);
        __syncthreads();

        const int nx = chunk + NSTAGES - 1;
        if (nx < NCHUNKS)
            load_stage(sbase + (nx & (NSTAGES - 1)) * STAGE_B, nx * KC,
                       nx == NCHUNKS - 1, ch, kcl, n_base, tid);
        CP_COMMIT();

        const uint32_t so = (uint32_t)(chunk & (NSTAGES - 1)) * STAGE_B;
        #pragma unroll
        for (int ks = 0; ks < 2; ++ks) {
            const int kb = ks * 32;
            uint32_t ah[2][4];
            LDSM4(ah[0], a_addr0 + so + kb);
            LDSM4(ah[1], a_addr0 + so + kb + 16 * ROWB);

            uint32_t bh[7][2];
            #pragma unroll
            for (int p = 0; p < 3; ++p) {
                uint32_t a = b_addr_pair0 + so + kb + (uint32_t)p * 16 * ROWB;
                uint32_t r4[4];
                LDSM4(r4, a);
                bh[2*p][0] = r4[0]; bh[2*p][1] = r4[1];
                bh[2*p+1][0] = r4[2]; bh[2*p+1][1] = r4[3];
            }
            LDSM2(bh[6], b_addr_last0 + so + kb);

            #pragma unroll
            for (int mf = 0; mf < 2; ++mf)
                #pragma unroll
                for (int nf = 0; nf < 7; ++nf)
                    MMA(acc[mf][nf], ah[mf], bh[nf]);
        }
    }

    // epilogue: bias + store
    const float* biasrow = bias + (size_t)kcl * P_DIM + n_base + nrow0;
    #pragma unroll
    for (int mf = 0; mf < 2; ++mf) {
        const int b0 = mrow0 + mf * 16 + (lane >> 2);   // batch rows b0, b0+8
        float* o0 = out + ((size_t)b0 * C_DIM + ch) * P_DIM + n_base + nrow0;
        float* o1 = o0 + (size_t)8 * C_DIM * P_DIM;
        #pragma unroll
        for (int nf = 0; nf < 7; ++nf) {
            const int col = nf * 8 + (lane & 3) * 2;
            float2 bb = *(const float2*)(biasrow + col);
            float2 v0, v1;
            v0.x = acc[mf][nf][0] + bb.x;
            v0.y = acc[mf][nf][1] + bb.y;
            v1.x = acc[mf][nf][2] + bb.x;
            v1.y = acc[mf][nf][3] + bb.y;
            *(float2*)(o0 + col) = v0;
            *(float2*)(o1 + col) = v1;
        }
    }
}

extern "C" void kernel_launch(void* const* d_in, const int* in_sizes, int n_in,
                              void* d_out, int out_size) {
    const float* x        = (const float*)d_in[0];
    const int*   clusters = (const int*)d_in[1];
    const float* W        = (const float*)d_in[2];
    const float* bias     = (const float*)d_in[3];
    float*       out      = (float*)d_out;

    cudaFuncSetAttribute(gemm_kernel, cudaFuncAttributeMaxDynamicSharedMemorySize, SMEM_TOTAL);

    convert_x<<<(int)(((size_t)B_DIM*C_DIM*S_DIM/4 + 255)/256), 256>>>(x);
    convert_w<<<(int)(((size_t)NCLUST*P_DIM*S_DIM/4 + 255)/256), 256>>>(W);
    gemm_kernel<<<dim3(3, C_DIM), 128, SMEM_TOTAL>>>(clusters, bias, out);
}